// round 17
// baseline (speedup 1.0000x reference)
#include <cuda_runtime.h>
#include <cuda_fp16.h>
#include <cuda_bf16.h>
#include <cstdint>

#define M_TOT 256
#define N_TOT 16384
#define K_TOT 4096
#define GPR   (K_TOT / 16)           // 256 groups per row
#define NCTAS 148
#define NSTRIP 7                     // strips/CTA (16 N cols each)

#define K_CHUNK 128                  // two k64 sub-tiles per chunk
#define NCHUNK (K_TOT / K_CHUNK)     // 32
#define THREADS 256
#define ROW_B 128                    // bytes per k64 sub-tile row (R12 swizzle)

#define ASUB (M_TOT * ROW_B)                 // 32768 per sub-tile
#define BSUB (NSTRIP * 16 * ROW_B)           // 14336 per sub-tile
#define A_BYTES (2 * ASUB)                   // 65536
#define B_BYTES (2 * BSUB)                   // 28672
#define SM_A0 0
#define SM_A1 (SM_A0 + A_BYTES)
#define SM_B0 (SM_A1 + A_BYTES)
#define SM_B1 (SM_B0 + B_BYTES)
#define SMEM_BYTES (SM_B1 + B_BYTES)         // 188416

#define NB_X 1024

// named barriers (id 0 reserved for __syncthreads):
//  FULL[slot] = 1+slot : stage(chunk in slot) complete/visible
//  FREE[slot] = 3+slot : all reads of chunk in slot done
#define BAR_CNT (2 * THREADS)
#define BAR_SYNC(id)   asm volatile("bar.sync %0, %1;"   :: "r"(id), "n"(BAR_CNT) : "memory")
#define BAR_ARRIVE(id) asm volatile("bar.arrive %0, %1;" :: "r"(id), "n"(BAR_CNT) : "memory")

// ---------------- device scratch ----------------
__device__ __half g_xh[M_TOT * K_TOT]; // x in fp16 (2 MB)
__device__ int    g_norm_dtype;        // 0=fp16, 1=bf16, 2=fp32

__device__ __forceinline__ uint32_t smem_u32(const void* p) {
    uint32_t a;
    asm("{ .reg .u64 t; cvta.to.shared.u64 t, %1; cvt.u32.u64 %0, t; }" : "=r"(a) : "l"(p));
    return a;
}
#define CP_ASYNC16(dst, src) \
    asm volatile("cp.async.cg.shared.global [%0], [%1], 16;" :: "r"(dst), "l"(src) : "memory")
#define CP_COMMIT() asm volatile("cp.async.commit_group;" ::: "memory")
#define CP_WAIT0()  asm volatile("cp.async.wait_group 0;" ::: "memory")
#define LDSM_X4(r0, r1, r2, r3, a) \
    asm volatile("ldmatrix.sync.aligned.m8n8.x4.shared.b16 {%0,%1,%2,%3}, [%4];" \
        : "=r"(r0), "=r"(r1), "=r"(r2), "=r"(r3) : "r"(a))
#define MMAF32(acc, a0, a1, a2, a3, b0, b1)                                    \
    asm volatile("mma.sync.aligned.m16n8k16.row.col.f32.f16.f16.f32 "          \
        "{%0,%1,%2,%3}, {%4,%5,%6,%7}, {%8,%9}, {%0,%1,%2,%3};\n"              \
        : "+f"((acc)[0]), "+f"((acc)[1]), "+f"((acc)[2]), "+f"((acc)[3])       \
        : "r"(a0), "r"(a1), "r"(a2), "r"(a3), "r"(b0), "r"(b1))

// ---------------- prepass: x fp32->fp16 + norm dtype detect ----------------
__global__ void prepass(const uint16_t* __restrict__ pnorm,
                        const float* __restrict__ x)
{
    const int tid = threadIdx.x;
    const int b = blockIdx.x;

    if (b == 0 && tid < 32) {
        bool okh = true, okb = true, bigh = false, bigb = false;
#pragma unroll
        for (int i = 0; i < 8; i++) {
            uint16_t r = pnorm[tid * 8 + i];
            float vh = __half2float(*(const __half*)&r);
            float vb = __bfloat162float(*(const __nv_bfloat16*)&r);
            okh &= (vh > 1e-6f && vh < 1.0f);
            okb &= (vb > 1e-6f && vb < 1.0f);
            bigh |= (vh > 0.1f);
            bigb |= (vb > 0.1f);
        }
        bool allh = __all_sync(0xffffffffu, okh);
        bool allb = __all_sync(0xffffffffu, okb);
        bool anyh = __any_sync(0xffffffffu, bigh);
        bool anyb = __any_sync(0xffffffffu, bigb);
        if (tid == 0)
            g_norm_dtype = (allh && anyh) ? 0 : ((allb && anyb) ? 1 : 2);
    }

    const int base = (b * 256 + tid) * 4;
    float4 v0 = *(const float4*)(x + base);
    __half2 o[2];
    o[0] = __floats2half2_rn(v0.x, v0.y);
    o[1] = __floats2half2_rn(v0.z, v0.w);
    *(uint2*)(g_xh + base) = *(uint2*)o;
}

// dequant one group's 4 packed words into 8 half2 words; nf = norm in fp32
__device__ __forceinline__ void dequant_group(const int4 q, float nf,
                                              uint32_t hv[8])
{
    const uint32_t MAGIC = 0x64006400u;
    const __half2  magic_h2 = *(const __half2*)&MAGIC;
    __half2 tc2 = __half2half2(__float2half_rn(nf * (2.0f / 3.0f)));
    __half2 m32 = __half2half2(__float2half_rn(-nf));
    int words[4] = {q.x, q.y, q.z, q.w};
#pragma unroll
    for (int w = 0; w < 4; w++) {
        uint32_t qq = (uint32_t)words[w];
        uint32_t u01 = MAGIC | (qq & 3u) | ((qq & 0xCu) << 14);
        uint32_t u23 = MAGIC | ((qq >> 4) & 3u) | ((qq & 0xC0u) << 10);
        __half2 v01 = __hsub2(*(__half2*)&u01, magic_h2);
        __half2 v23 = __hsub2(*(__half2*)&u23, magic_h2);
        __half2 w01 = __hfma2(v01, tc2, m32);
        __half2 w23 = __hfma2(v23, tc2, m32);
        hv[w * 2]     = *(uint32_t*)&w01;
        hv[w * 2 + 1] = *(uint32_t*)&w23;
    }
}

// ---------------- main GEMM: R14 + split named barriers ----------------
__global__ __launch_bounds__(THREADS, 1)
void l2b_hmma(const int4* __restrict__ wq,
              const uint16_t* __restrict__ pnorm,
              const __half* __restrict__ xh,
              const float* __restrict__ bias,
              float* __restrict__ out)
{
    extern __shared__ char smem[];
    const uint32_t sb = smem_u32(smem);
    const int tid  = threadIdx.x;
    const int lane = tid & 31;
    const int warp = tid >> 5;        // 0..7 : 32 M rows each, all 7 strips
    const int bid  = blockIdx.x;

    const int nbase = bid * (NSTRIP * 16);
    const int dt = g_norm_dtype;

    float acc[2][NSTRIP][2][4];
#pragma unroll
    for (int mi = 0; mi < 2; mi++)
#pragma unroll
        for (int si = 0; si < NSTRIP; si++)
#pragma unroll
            for (int e = 0; e < 2; e++)
#pragma unroll
                for (int r = 0; r < 4; r++) acc[mi][si][e][r] = 0.f;

    int4     qr[2];
    uint32_t nr[2];
    const bool has1 = (tid + 256) < NSTRIP * 64;

    // A staging: per chunk, 4096 16B segs = 2 subs x (256 rows x 8 segs)
    auto issueA = [&](int c, uint32_t abase) {
#pragma unroll
        for (int h = 0; h < 16; h++) {
            int sub = h >> 3;
            int seg = tid + (h & 7) * 256;
            int row = seg >> 3;
            int s   = seg & 7;
            const __half* src = xh + (size_t)row * K_TOT + c * K_CHUNK + sub * 64 + s * 8;
            uint32_t dst = abase + sub * ASUB + row * ROW_B + ((s ^ (row & 7)) << 4);
            CP_ASYNC16(dst, src);
        }
        CP_COMMIT();
    };
    // B weight load for (chunk c, sub-tile s): k64 index = 2c + s
    auto loadW = [&](int c, int s) {
        int k64 = c * 2 + s;
        {
            int col = nbase + (tid >> 2);
            col = col < N_TOT ? col : N_TOT - 1;
            int g   = col * GPR + k64 * 4 + (tid & 3);
            qr[0] = wq[g];
            if (dt == 2) nr[0] = ((const uint32_t*)pnorm)[g];
            else         nr[0] = pnorm[g];
        }
        if (has1) {
            int col = nbase + ((tid + 256) >> 2);
            col = col < N_TOT ? col : N_TOT - 1;
            int g   = col * GPR + k64 * 4 + (tid & 3);
            qr[1] = wq[g];
            if (dt == 2) nr[1] = ((const uint32_t*)pnorm)[g];
            else         nr[1] = pnorm[g];
        }
    };
    auto rawToF = [&](uint32_t r) -> float {
        if (dt == 0)      return __half2float(__ushort_as_half((unsigned short)r));
        else if (dt == 1) return __uint_as_float(r << 16);
        else              return __uint_as_float(r);
    };

    // STS addressing (R12 swizzle, per sub-tile)
    const uint32_t g0_wn = tid >> 2, g0_wgi = tid & 3;
    const uint32_t g1_wn = g0_wn + 64;
    const uint32_t sts00 = g0_wn * ROW_B + (((2 * g0_wgi) ^ (g0_wn & 7)) << 4);
    const uint32_t sts01 = g0_wn * ROW_B + (((2 * g0_wgi + 1) ^ (g0_wn & 7)) << 4);
    const uint32_t sts10 = g1_wn * ROW_B + (((2 * g0_wgi) ^ (g1_wn & 7)) << 4);
    const uint32_t sts11 = g1_wn * ROW_B + (((2 * g0_wgi + 1) ^ (g1_wn & 7)) << 4);

    auto stsB0 = [&](uint32_t bsubbase) {
        uint32_t hv[8];
        dequant_group(qr[0], rawToF(nr[0]), hv);
        asm volatile("st.shared.v4.b32 [%0], {%1,%2,%3,%4};"
            :: "r"(bsubbase + sts00), "r"(hv[0]), "r"(hv[1]), "r"(hv[2]), "r"(hv[3]) : "memory");
        asm volatile("st.shared.v4.b32 [%0], {%1,%2,%3,%4};"
            :: "r"(bsubbase + sts01), "r"(hv[4]), "r"(hv[5]), "r"(hv[6]), "r"(hv[7]) : "memory");
    };
    auto stsB1 = [&](uint32_t bsubbase) {
        if (has1) {
            uint32_t hv[8];
            dequant_group(qr[1], rawToF(nr[1]), hv);
            asm volatile("st.shared.v4.b32 [%0], {%1,%2,%3,%4};"
                :: "r"(bsubbase + sts10), "r"(hv[0]), "r"(hv[1]), "r"(hv[2]), "r"(hv[3]) : "memory");
            asm volatile("st.shared.v4.b32 [%0], {%1,%2,%3,%4};"
                :: "r"(bsubbase + sts11), "r"(hv[4]), "r"(hv[5]), "r"(hv[6]), "r"(hv[7]) : "memory");
        }
    };

    // LDSM addressing (R12 swizzle, per sub-tile)
    uint32_t a_rb[2], a_x7[2];
#pragma unroll
    for (int mi = 0; mi < 2; mi++) {
        int r = warp * 32 + mi * 16 + (lane & 15);
        a_rb[mi] = (uint32_t)r * ROW_B;
        a_x7[mi] = (uint32_t)(r & 7);
    }
    const uint32_t a_wb = (lane >> 4) & 1;
    const uint32_t b_nl = (uint32_t)((lane & 7) | ((lane & 16) >> 1));
    const uint32_t b_rb = b_nl * ROW_B;
    const uint32_t b_x7 = b_nl & 7;
    const uint32_t b_wb = (lane >> 3) & 1;

    // ---- prologue: stage chunk 0 into slot 0; declare slot 1 free
    issueA(0, sb + SM_A0);
    loadW(0, 0);
    stsB0(sb + SM_B0);
    stsB1(sb + SM_B0);
    loadW(0, 1);
    stsB0(sb + SM_B0 + BSUB);
    stsB1(sb + SM_B0 + BSUB);
    CP_WAIT0();
    BAR_ARRIVE(1);     // FULL[0]
    BAR_ARRIVE(4);     // FREE[1]

    for (int c = 0; c < NCHUNK; ++c) {
        const int s  = c & 1;
        const int ns = s ^ 1;
        const uint32_t abase  = sb + (s ? SM_A1 : SM_A0);
        const uint32_t bbase  = sb + (s ? SM_B1 : SM_B0);
        const uint32_t anext  = sb + (s ? SM_A0 : SM_A1);
        const uint32_t bnext  = sb + (s ? SM_B0 : SM_B1);
        const bool more = (c + 1 < NCHUNK);

        BAR_SYNC(1 + s);   // FULL[s]: chunk c staged & visible

        // ---- compute chunk c: 8 k-steps; chunk c+1 staged into slot ns in shadow
#pragma unroll
        for (int ks = 0; ks < 8; ++ks) {
            const uint32_t asub = abase + (ks >> 2) * ASUB;
            const uint32_t bsub = bbase + (ks >> 2) * BSUB;
            const uint32_t ksl = ks & 3;
            uint32_t a0, a1, a2, a3, a4, a5, a6, a7;
            {
                uint32_t w = ksl * 2 + a_wb;
                LDSM_X4(a0, a1, a2, a3, asub + a_rb[0] + ((w ^ a_x7[0]) << 4));
                LDSM_X4(a4, a5, a6, a7, asub + a_rb[1] + ((w ^ a_x7[1]) << 4));
            }
#pragma unroll
            for (int si = 0; si < NSTRIP; si++) {
                uint32_t b0, b1, b2, b3;
                {
                    uint32_t w = ksl * 2 + b_wb;
                    LDSM_X4(b0, b1, b2, b3,
                            bsub + (uint32_t)si * (16 * ROW_B) + b_rb + ((w ^ b_x7) << 4));
                }
#pragma unroll
                for (int e = 0; e < 2; e++) {
                    uint32_t bb0 = e ? b2 : b0;
                    uint32_t bb1 = e ? b3 : b1;
                    MMAF32(acc[0][si][e], a0, a1, a2, a3, bb0, bb1);
                    MMAF32(acc[1][si][e], a4, a5, a6, a7, bb0, bb1);
                }
            }
            if (more) {
                if (ks == 1) {
                    BAR_SYNC(3 + ns);        // FREE[ns]: all reads of chunk c-1 done
                    issueA(c + 1, anext);
                    loadW(c + 1, 0);
                }
                if (ks == 2) stsB0(bnext);
                if (ks == 3) { stsB1(bnext); loadW(c + 1, 1); }
                if (ks == 5) stsB0(bnext + BSUB);
                if (ks == 6) {
                    stsB1(bnext + BSUB);
                    CP_WAIT0();              // own A(c+1) copies done
                    BAR_ARRIVE(1 + ns);      // FULL[ns]: my staging complete
                }
            }
        }

        if (more) BAR_ARRIVE(3 + s);         // FREE[s]: my reads of chunk c done
    }

    // ---- epilogue: bias + fp32 store (guarded for padded N)
#pragma unroll
    for (int mi = 0; mi < 2; mi++) {
        int r = warp * 32 + mi * 16 + (lane >> 2);
#pragma unroll
        for (int si = 0; si < NSTRIP; si++) {
#pragma unroll
            for (int e = 0; e < 2; e++) {
                int ncol = nbase + si * 16 + e * 8 + (lane & 3) * 2;
                if (ncol < N_TOT) {
                    float b0 = bias[ncol];
                    float b1 = bias[ncol + 1];
                    float2* o0 = (float2*)(out + (size_t)r * N_TOT + ncol);
                    float2* o1 = (float2*)(out + (size_t)(r + 8) * N_TOT + ncol);
                    *o0 = make_float2(acc[mi][si][e][0] + b0, acc[mi][si][e][1] + b1);
                    *o1 = make_float2(acc[mi][si][e][2] + b0, acc[mi][si][e][3] + b1);
                }
            }
        }
    }
}

// ---------------- launcher ----------------
extern "C" void kernel_launch(void* const* d_in, const int* in_sizes, int n_in,
                              void* d_out, int out_size)
{
    // Bind by size order: wq > norm > x > bias
    int order[4] = {0, 1, 2, 3};
    for (int i = 1; i < 4 && i < n_in; i++) {
        int v = order[i], j = i - 1;
        while (j >= 0 && (long long)in_sizes[order[j]] < (long long)in_sizes[v]) {
            order[j + 1] = order[j]; j--;
        }
        order[j + 1] = v;
    }
    const int4*     wq    = (const int4*)d_in[order[0]];
    const uint16_t* pnorm = (const uint16_t*)d_in[order[1]];
    const float*    x     = (const float*)d_in[order[2]];
    const float*    bias  = (const float*)d_in[order[3]];
    float* out = (float*)d_out;

    prepass<<<NB_X, 256>>>(pnorm, x);

    __half* xh_dev = nullptr;
    cudaGetSymbolAddress((void**)&xh_dev, g_xh);

    cudaFuncSetAttribute(l2b_hmma, cudaFuncAttributeMaxDynamicSharedMemorySize, SMEM_BYTES);
    l2b_hmma<<<NCTAS, THREADS, SMEM_BYTES>>>(wq, pnorm, xh_dev, bias, out);
}